// round 4
// baseline (speedup 1.0000x reference)
#include <cuda_runtime.h>
#include <math.h>

// Problem constants
static constexpr int NN   = 10000;
static constexpr int EE   = 320000;
static constexpr int EN   = EE + NN;        // edges + self loops
static constexpr int IND  = 512;
static constexpr int HIDD = 128;
static constexpr int OUTD = 128;
static constexpr int HEADS = 4;
static constexpr int GC    = 64;
static constexpr int FEAT  = HEADS * GC;    // 256
static constexpr float NEG_SLOPE = 0.2f;
static constexpr int MAXDEG = 192;          // smem cache cap (deg ~ Poisson(33))
static constexpr int SCAN_BLKS = 40;        // 40*256 = 10240 >= NN

// -------- scratch (device globals: no allocation allowed) --------
__device__ float d_h1[(size_t)NN * HIDD];
__device__ float d_h2[(size_t)NN * OUTD];
__device__ float d_g [(size_t)NN * FEAT];
__device__ float d_asrc[NN * HEADS];
__device__ float d_adst[NN * HEADS];
__device__ int   d_cnt[NN];          // histogram, then reused as fill cursor
__device__ int   d_off[NN + 1];      // CSR offsets
__device__ int   d_bsum[SCAN_BLKS];  // scan block partials
__device__ int   d_src_csr[EN];      // src node per CSR slot
__device__ int   d_is64;

// -------- helpers --------
__device__ __forceinline__ void load_edge(const void* ei, int is64, int tid,
                                          int& s, int& d) {
    if (tid < EE) {
        if (is64) {
            const long long* p = (const long long*)ei;
            s = (int)p[tid];
            d = (int)p[EE + tid];
        } else {
            const int* p = (const int*)ei;
            s = p[tid];
            d = p[EE + tid];
        }
    } else {
        s = d = tid - EE;
    }
}

// -------- setup: zero histogram + detect int64 vs int32 edge_index --------
__global__ void setup_kernel(const int* ei) {
    int idx = blockIdx.x * blockDim.x + threadIdx.x;
    if (idx < NN) d_cnt[idx] = 0;
    if (idx == 0) {
        int ok64 = 1;
        for (int i = 1; i < 256; i += 2)
            if (ei[i] != 0) { ok64 = 0; break; }
        d_is64 = ok64;
    }
}

__global__ void count_kernel(const void* __restrict__ ei) {
    int tid = blockIdx.x * blockDim.x + threadIdx.x;
    if (tid >= EN) return;
    int s, d;
    load_edge(ei, d_is64, tid, s, d);
    atomicAdd(&d_cnt[d], 1);
}

// -------- 3-phase exclusive scan of d_cnt -> d_off --------
__global__ void scanA_kernel() {
    __shared__ int sh[256];
    const int t = threadIdx.x;
    const int idx = blockIdx.x * 256 + t;
    int v = (idx < NN) ? d_cnt[idx] : 0;
    sh[t] = v;
    __syncthreads();
    #pragma unroll
    for (int o = 1; o < 256; o <<= 1) {
        int u = (t >= o) ? sh[t - o] : 0;
        __syncthreads();
        sh[t] += u;
        __syncthreads();
    }
    if (idx < NN) d_off[idx] = sh[t] - v;      // local exclusive
    if (t == 255) d_bsum[blockIdx.x] = sh[255];
}

__global__ void scanB_kernel() {    // 1 block, 64 threads
    __shared__ int sh[64];
    const int t = threadIdx.x;
    int v = (t < SCAN_BLKS) ? d_bsum[t] : 0;
    sh[t] = v;
    __syncthreads();
    #pragma unroll
    for (int o = 1; o < 64; o <<= 1) {
        int u = (t >= o) ? sh[t - o] : 0;
        __syncthreads();
        sh[t] += u;
        __syncthreads();
    }
    if (t < SCAN_BLKS) d_bsum[t] = sh[t] - v;  // exclusive block offsets
    if (t == 63) d_off[NN] = sh[63];           // total (= EN)
}

__global__ void scanC_kernel() {
    int idx = blockIdx.x * 256 + threadIdx.x;
    if (idx < NN) {
        d_off[idx] += d_bsum[blockIdx.x];
        d_cnt[idx] = 0;                        // reset for fill cursor
    }
}

__global__ void fill_kernel(const void* __restrict__ ei) {
    int tid = blockIdx.x * blockDim.x + threadIdx.x;
    if (tid >= EN) return;
    int s, d;
    load_edge(ei, d_is64, tid, s, d);
    int pos = atomicAdd(&d_cnt[d], 1);
    d_src_csr[d_off[d] + pos] = s;
}

// -------- tiled fp32 GEMM: BM=64, BN=128, BK=16, 256 thr, 4x8 micro --------
// Requires K % 16 == 0, Nc % 128 == 0.
__global__ void __launch_bounds__(256) gemm_bias_act(
        const float* __restrict__ A, const float* __restrict__ B,
        const float* __restrict__ bias, float* __restrict__ C,
        int M, int Nc, int K, int do_relu) {
    __shared__ float As[16][68];    // transposed: As[k][m], padded row
    __shared__ float Bs[16][132];   // Bs[k][n], padded row

    const int t  = threadIdx.x;
    const int tx = t & 15;          // 0..15 -> n micro
    const int ty = t >> 4;          // 0..15 -> m micro
    const int m0 = blockIdx.y * 64;
    const int n0 = blockIdx.x * 128;

    const int aRow = t >> 2;            // 0..63
    const int aCol = (t & 3) * 4;       // k offset
    const int bRow = t >> 4;            // 0..15
    const int bCol = (t & 15) * 8;      // 0..120

    float acc[4][8] = {};

    for (int k0 = 0; k0 < K; k0 += 16) {
        // load A tile (transposed into As[k][m])
        {
            float4 v;
            if (m0 + aRow < M)
                v = *(const float4*)&A[(size_t)(m0 + aRow) * K + k0 + aCol];
            else
                v = make_float4(0.f, 0.f, 0.f, 0.f);
            As[aCol + 0][aRow] = v.x;
            As[aCol + 1][aRow] = v.y;
            As[aCol + 2][aRow] = v.z;
            As[aCol + 3][aRow] = v.w;
        }
        // load B tile
        {
            const float* bp = &B[(size_t)(k0 + bRow) * Nc + n0 + bCol];
            *(float4*)&Bs[bRow][bCol]     = *(const float4*)bp;
            *(float4*)&Bs[bRow][bCol + 4] = *(const float4*)(bp + 4);
        }
        __syncthreads();

        #pragma unroll
        for (int k = 0; k < 16; k++) {
            float4 a4 = *(const float4*)&As[k][ty * 4];
            float4 bl = *(const float4*)&Bs[k][tx * 8];
            float4 bh = *(const float4*)&Bs[k][tx * 8 + 4];
            float a[4] = {a4.x, a4.y, a4.z, a4.w};
            float b[8] = {bl.x, bl.y, bl.z, bl.w, bh.x, bh.y, bh.z, bh.w};
            #pragma unroll
            for (int i = 0; i < 4; i++)
                #pragma unroll
                for (int j = 0; j < 8; j++)
                    acc[i][j] = fmaf(a[i], b[j], acc[i][j]);
        }
        __syncthreads();
    }

    #pragma unroll
    for (int i = 0; i < 4; i++) {
        int row = m0 + ty * 4 + i;
        if (row >= M) continue;
        float* cp = &C[(size_t)row * Nc + n0 + tx * 8];
        float o[8];
        #pragma unroll
        for (int j = 0; j < 8; j++) {
            float v = acc[i][j];
            if (bias) v += bias[n0 + tx * 8 + j];
            if (do_relu) v = fmaxf(v, 0.f);
            o[j] = v;
        }
        *(float4*)cp       = make_float4(o[0], o[1], o[2], o[3]);
        *(float4*)(cp + 4) = make_float4(o[4], o[5], o[6], o[7]);
    }
}

// -------- per-node attention coefficients: one warp per (node, head) --------
__global__ void attn_coef_kernel(const float* __restrict__ att_src,
                                 const float* __restrict__ att_dst) {
    int warp = (blockIdx.x * blockDim.x + threadIdx.x) >> 5;
    int lane = threadIdx.x & 31;
    if (warp >= NN * HEADS) return;
    int n = warp / HEADS, h = warp % HEADS;
    const float* gp = d_g + (size_t)n * FEAT + h * GC;
    float ss = 0.f, sd = 0.f;
    #pragma unroll
    for (int c = lane; c < GC; c += 32) {
        float gv = gp[c];
        ss += gv * att_src[h * GC + c];
        sd += gv * att_dst[h * GC + c];
    }
    #pragma unroll
    for (int o = 16; o; o >>= 1) {
        ss += __shfl_xor_sync(0xFFFFFFFFu, ss, o);
        sd += __shfl_xor_sync(0xFFFFFFFFu, sd, o);
    }
    if (lane == 0) {
        d_asrc[n * HEADS + h] = ss;
        d_adst[n * HEADS + h] = sd;
    }
}

// -------- single-pass gather: 64 threads per node, 4 nodes per block ------
// out[node] = (1/psum) * sum_j ex_j * g[src_j]  + bias
__global__ void __launch_bounds__(256) gather_kernel(float* __restrict__ out,
                                                     const float* __restrict__ bias_g) {
    __shared__ int s_src[4][MAXDEG];

    const int grp  = threadIdx.x >> 6;       // node slot in block
    const int t    = threadIdx.x & 63;       // channel quad owner
    const int node = blockIdx.x * 4 + grp;   // NN % 4 == 0
    const int h    = t >> 4;                 // head of my channels

    const int beg = d_off[node];
    const int deg = d_off[node + 1] - beg;
    const int cached = (deg < MAXDEG) ? deg : MAXDEG;

    for (int j = t; j < cached; j += 64)
        s_src[grp][j] = d_src_csr[beg + j];
    __syncthreads();

    const float adst_h = d_adst[node * HEADS + h];

    float4 acc = make_float4(0.f, 0.f, 0.f, 0.f);
    float psum = 0.f;
    #pragma unroll 4
    for (int j = 0; j < deg; j++) {
        int s = (j < MAXDEG) ? s_src[grp][j] : d_src_csr[beg + j];
        float e = d_asrc[s * HEADS + h] + adst_h;
        e = (e > 0.f) ? e : NEG_SLOPE * e;
        float ex = __expf(e);
        psum += ex;
        float4 gv = *(const float4*)&d_g[(size_t)s * FEAT + 4 * t];
        acc.x = fmaf(gv.x, ex, acc.x);
        acc.y = fmaf(gv.y, ex, acc.y);
        acc.z = fmaf(gv.z, ex, acc.z);
        acc.w = fmaf(gv.w, ex, acc.w);
    }
    const float inv = __frcp_rn(psum);       // deg >= 1 (self loop)

    float4 bv = *(const float4*)&bias_g[4 * t];
    float4 res;
    res.x = fmaf(acc.x, inv, bv.x);
    res.y = fmaf(acc.y, inv, bv.y);
    res.z = fmaf(acc.z, inv, bv.z);
    res.w = fmaf(acc.w, inv, bv.w);
    *(float4*)&out[(size_t)node * FEAT + 4 * t] = res;
}

// ----------------------------------------------------------------------------
extern "C" void kernel_launch(void* const* d_in, const int* in_sizes, int n_in,
                              void* d_out, int out_size) {
    const float* x        = (const float*)d_in[0];
    const void*  ei       = d_in[1];
    const float* W1       = (const float*)d_in[2];
    const float* b1       = (const float*)d_in[3];
    const float* W2       = (const float*)d_in[4];
    const float* b2       = (const float*)d_in[5];
    const float* Wg       = (const float*)d_in[6];
    const float* att_src  = (const float*)d_in[7];
    const float* att_dst  = (const float*)d_in[8];
    const float* bias_g   = (const float*)d_in[9];
    float* out = (float*)d_out;

    void *p_h1, *p_h2, *p_g;
    cudaGetSymbolAddress(&p_h1, d_h1);
    cudaGetSymbolAddress(&p_h2, d_h2);
    cudaGetSymbolAddress(&p_g,  d_g);

    // CSR build
    setup_kernel<<<SCAN_BLKS, 256>>>((const int*)ei);
    count_kernel<<<(EN + 255) / 256, 256>>>(ei);
    scanA_kernel<<<SCAN_BLKS, 256>>>();
    scanB_kernel<<<1, 64>>>();
    scanC_kernel<<<SCAN_BLKS, 256>>>();
    fill_kernel<<<(EN + 255) / 256, 256>>>(ei);

    // encoder: h1 = relu(x@W1 + b1) ; h2 = h1@W2 + b2 ; g = h2@Wg
    {
        dim3 grid(HIDD / 128, (NN + 63) / 64);
        gemm_bias_act<<<grid, 256>>>(x, W1, b1, (float*)p_h1, NN, HIDD, IND, 1);
    }
    {
        dim3 grid(OUTD / 128, (NN + 63) / 64);
        gemm_bias_act<<<grid, 256>>>((const float*)p_h1, W2, b2, (float*)p_h2,
                                     NN, OUTD, HIDD, 0);
    }
    {
        dim3 grid(FEAT / 128, (NN + 63) / 64);
        gemm_bias_act<<<grid, 256>>>((const float*)p_h2, Wg, nullptr, (float*)p_g,
                                     NN, FEAT, OUTD, 0);
    }

    // attention coefficients
    {
        int warps = NN * HEADS;
        attn_coef_kernel<<<(warps * 32 + 255) / 256, 256>>>(att_src, att_dst);
    }

    // softmax + aggregation in one pass (no output atomics)
    gather_kernel<<<NN / 4, 256>>>(out, bias_g);
}

// round 5
// speedup vs baseline: 2.1141x; 2.1141x over previous
#include <cuda_runtime.h>
#include <math.h>

// Problem constants
static constexpr int NN   = 10000;
static constexpr int EE   = 320000;
static constexpr int EN   = EE + NN;        // edges + self loops
static constexpr int IND  = 512;
static constexpr int HIDD = 128;
static constexpr int OUTD = 128;
static constexpr int HEADS = 4;
static constexpr int GC    = 64;
static constexpr int FEAT  = HEADS * GC;    // 256
static constexpr float NEG_SLOPE = 0.2f;
static constexpr int MAXDEG = 256;          // smem cache cap (deg ~ Poisson(33))
static constexpr int SCAN_BLKS = 40;        // 40*256 = 10240 >= NN

// -------- scratch (device globals: no allocation allowed) --------
__device__ float d_h1[(size_t)NN * HIDD];
__device__ float d_h2[(size_t)NN * OUTD];
__device__ float d_g [(size_t)NN * FEAT];
__device__ float d_asrc[NN * HEADS];
__device__ float d_adst[NN * HEADS];
__device__ int   d_cnt[NN];          // histogram, then reused as fill cursor
__device__ int   d_off[NN + 1];      // CSR offsets
__device__ int   d_bsum[SCAN_BLKS];  // scan block partials
__device__ int   d_src_csr[EN];      // src node per CSR slot
__device__ int   d_is64;

// -------- helpers --------
__device__ __forceinline__ void load_edge(const void* ei, int is64, int tid,
                                          int& s, int& d) {
    if (tid < EE) {
        if (is64) {
            const long long* p = (const long long*)ei;
            s = (int)p[tid];
            d = (int)p[EE + tid];
        } else {
            const int* p = (const int*)ei;
            s = p[tid];
            d = p[EE + tid];
        }
    } else {
        s = d = tid - EE;
    }
}

// -------- setup: zero histogram + detect int64 vs int32 edge_index --------
__global__ void setup_kernel(const int* ei) {
    int idx = blockIdx.x * blockDim.x + threadIdx.x;
    if (idx < NN) d_cnt[idx] = 0;
    if (idx == 0) {
        int ok64 = 1;
        for (int i = 1; i < 256; i += 2)
            if (ei[i] != 0) { ok64 = 0; break; }
        d_is64 = ok64;
    }
}

__global__ void count_kernel(const void* __restrict__ ei) {
    int tid = blockIdx.x * blockDim.x + threadIdx.x;
    if (tid >= EN) return;
    int s, d;
    load_edge(ei, d_is64, tid, s, d);
    atomicAdd(&d_cnt[d], 1);
}

// -------- 3-phase exclusive scan of d_cnt -> d_off --------
__global__ void scanA_kernel() {
    __shared__ int sh[256];
    const int t = threadIdx.x;
    const int idx = blockIdx.x * 256 + t;
    int v = (idx < NN) ? d_cnt[idx] : 0;
    sh[t] = v;
    __syncthreads();
    #pragma unroll
    for (int o = 1; o < 256; o <<= 1) {
        int u = (t >= o) ? sh[t - o] : 0;
        __syncthreads();
        sh[t] += u;
        __syncthreads();
    }
    if (idx < NN) d_off[idx] = sh[t] - v;      // local exclusive
    if (t == 255) d_bsum[blockIdx.x] = sh[255];
}

__global__ void scanB_kernel() {    // 1 block, 64 threads
    __shared__ int sh[64];
    const int t = threadIdx.x;
    int v = (t < SCAN_BLKS) ? d_bsum[t] : 0;
    sh[t] = v;
    __syncthreads();
    #pragma unroll
    for (int o = 1; o < 64; o <<= 1) {
        int u = (t >= o) ? sh[t - o] : 0;
        __syncthreads();
        sh[t] += u;
        __syncthreads();
    }
    if (t < SCAN_BLKS) d_bsum[t] = sh[t] - v;  // exclusive block offsets
    if (t == 63) d_off[NN] = sh[63];           // total (= EN)
}

__global__ void scanC_kernel() {
    int idx = blockIdx.x * 256 + threadIdx.x;
    if (idx < NN) {
        d_off[idx] += d_bsum[blockIdx.x];
        d_cnt[idx] = 0;                        // reset for fill cursor
    }
}

__global__ void fill_kernel(const void* __restrict__ ei) {
    int tid = blockIdx.x * blockDim.x + threadIdx.x;
    if (tid >= EN) return;
    int s, d;
    load_edge(ei, d_is64, tid, s, d);
    int pos = atomicAdd(&d_cnt[d], 1);
    d_src_csr[d_off[d] + pos] = s;
}

// -------- tiled fp32 GEMM: C[M,Nc] = A[M,K] @ B[K,Nc] (+bias)(+relu) --------
// BM=64, BN=64, BK=16, 256 threads, 4x4 micro-tile.  (proven R3 version)
__global__ void gemm_bias_act(const float* __restrict__ A,
                              const float* __restrict__ B,
                              const float* __restrict__ bias,
                              float* __restrict__ C,
                              int M, int Nc, int K, int do_relu) {
    __shared__ float As[64][17];
    __shared__ float Bs[16][64];

    const int t  = threadIdx.x;
    const int tx = t & 15;
    const int ty = t >> 4;
    const int m0 = blockIdx.y * 64;
    const int n0 = blockIdx.x * 64;

    const int aRow = t >> 2;
    const int aCol = (t & 3) * 4;
    const int bRow = t >> 4;
    const int bCol = (t & 15) * 4;

    float acc[4][4] = {};

    for (int k0 = 0; k0 < K; k0 += 16) {
        if (m0 + aRow < M) {
            float4 v = *(const float4*)&A[(size_t)(m0 + aRow) * K + k0 + aCol];
            As[aRow][aCol + 0] = v.x; As[aRow][aCol + 1] = v.y;
            As[aRow][aCol + 2] = v.z; As[aRow][aCol + 3] = v.w;
        } else {
            As[aRow][aCol + 0] = 0.f; As[aRow][aCol + 1] = 0.f;
            As[aRow][aCol + 2] = 0.f; As[aRow][aCol + 3] = 0.f;
        }
        {
            float4 v = *(const float4*)&B[(size_t)(k0 + bRow) * Nc + n0 + bCol];
            Bs[bRow][bCol + 0] = v.x; Bs[bRow][bCol + 1] = v.y;
            Bs[bRow][bCol + 2] = v.z; Bs[bRow][bCol + 3] = v.w;
        }
        __syncthreads();

        #pragma unroll
        for (int k = 0; k < 16; k++) {
            float a[4], b[4];
            #pragma unroll
            for (int i = 0; i < 4; i++) a[i] = As[ty * 4 + i][k];
            #pragma unroll
            for (int j = 0; j < 4; j++) b[j] = Bs[k][tx * 4 + j];
            #pragma unroll
            for (int i = 0; i < 4; i++)
                #pragma unroll
                for (int j = 0; j < 4; j++)
                    acc[i][j] = fmaf(a[i], b[j], acc[i][j]);
        }
        __syncthreads();
    }

    #pragma unroll
    for (int i = 0; i < 4; i++) {
        int row = m0 + ty * 4 + i;
        if (row >= M) continue;
        #pragma unroll
        for (int j = 0; j < 4; j++) {
            int col = n0 + tx * 4 + j;
            float v = acc[i][j];
            if (bias) v += bias[col];
            if (do_relu) v = fmaxf(v, 0.f);
            C[(size_t)row * Nc + col] = v;
        }
    }
}

// -------- per-node attention coefficients: one warp per (node, head) --------
__global__ void attn_coef_kernel(const float* __restrict__ att_src,
                                 const float* __restrict__ att_dst) {
    int warp = (blockIdx.x * blockDim.x + threadIdx.x) >> 5;
    int lane = threadIdx.x & 31;
    if (warp >= NN * HEADS) return;
    int n = warp / HEADS, h = warp % HEADS;
    const float* gp = d_g + (size_t)n * FEAT + h * GC;
    float ss = 0.f, sd = 0.f;
    #pragma unroll
    for (int c = lane; c < GC; c += 32) {
        float gv = gp[c];
        ss += gv * att_src[h * GC + c];
        sd += gv * att_dst[h * GC + c];
    }
    #pragma unroll
    for (int o = 16; o; o >>= 1) {
        ss += __shfl_xor_sync(0xFFFFFFFFu, ss, o);
        sd += __shfl_xor_sync(0xFFFFFFFFu, sd, o);
    }
    if (lane == 0) {
        d_asrc[n * HEADS + h] = ss;
        d_adst[n * HEADS + h] = sd;
    }
}

// -------- gather aggregation (proven R3 two-pass version) --------
__global__ void __launch_bounds__(256) gather_kernel(float* __restrict__ out,
                                                     const float* __restrict__ bias_g) {
    __shared__ float s_ex[4][MAXDEG * HEADS];
    __shared__ int   s_src[4][MAXDEG];

    const int grp  = threadIdx.x >> 6;       // node slot in block
    const int t    = threadIdx.x & 63;       // channel quad owner
    const int node = blockIdx.x * 4 + grp;   // NN % 4 == 0
    const int h    = t >> 4;                 // head of my channels
    const int l16  = t & 15;

    const int beg = d_off[node];
    const int deg = d_off[node + 1] - beg;
    const int cached = (deg < MAXDEG) ? deg : MAXDEG;

    for (int j = t; j < cached; j += 64)
        s_src[grp][j] = d_src_csr[beg + j];
    __syncthreads();

    const float adst_h = d_adst[node * HEADS + h];

    // pass 1: ex per (edge, my head), partial softmax sum over 16 lanes
    float psum = 0.f;
    for (int j = l16; j < deg; j += 16) {
        int s = (j < MAXDEG) ? s_src[grp][j] : d_src_csr[beg + j];
        float e = d_asrc[s * HEADS + h] + adst_h;
        e = (e > 0.f) ? e : NEG_SLOPE * e;
        float ex = __expf(e);
        if (j < MAXDEG) s_ex[grp][j * HEADS + h] = ex;
        psum += ex;
    }
    #pragma unroll
    for (int o = 8; o; o >>= 1)
        psum += __shfl_xor_sync(0xFFFFFFFFu, psum, o);
    const float inv = __frcp_rn(psum);       // deg >= 1 (self loop)
    __syncthreads();

    // pass 2: accumulate alpha-weighted g[src] rows (streaming, high MLP)
    float4 acc = make_float4(0.f, 0.f, 0.f, 0.f);
    for (int j = 0; j < deg; j++) {
        float ex;
        int s;
        if (j < MAXDEG) {
            ex = s_ex[grp][j * HEADS + h];
            s  = s_src[grp][j];
        } else {
            s = d_src_csr[beg + j];
            float e = d_asrc[s * HEADS + h] + adst_h;
            e = (e > 0.f) ? e : NEG_SLOPE * e;
            ex = __expf(e);
        }
        float alpha = ex * inv;
        float4 gv = *(const float4*)&d_g[(size_t)s * FEAT + 4 * t];
        acc.x = fmaf(gv.x, alpha, acc.x);
        acc.y = fmaf(gv.y, alpha, acc.y);
        acc.z = fmaf(gv.z, alpha, acc.z);
        acc.w = fmaf(gv.w, alpha, acc.w);
    }

    float4 bv = *(const float4*)&bias_g[4 * t];
    acc.x += bv.x; acc.y += bv.y; acc.z += bv.z; acc.w += bv.w;
    *(float4*)&out[(size_t)node * FEAT + 4 * t] = acc;
}

// ----------------------------------------------------------------------------
extern "C" void kernel_launch(void* const* d_in, const int* in_sizes, int n_in,
                              void* d_out, int out_size) {
    const float* x        = (const float*)d_in[0];
    const void*  ei       = d_in[1];
    const float* W1       = (const float*)d_in[2];
    const float* b1       = (const float*)d_in[3];
    const float* W2       = (const float*)d_in[4];
    const float* b2       = (const float*)d_in[5];
    const float* Wg       = (const float*)d_in[6];
    const float* att_src  = (const float*)d_in[7];
    const float* att_dst  = (const float*)d_in[8];
    const float* bias_g   = (const float*)d_in[9];
    float* out = (float*)d_out;

    void *p_h1, *p_h2, *p_g;
    cudaGetSymbolAddress(&p_h1, d_h1);
    cudaGetSymbolAddress(&p_h2, d_h2);
    cudaGetSymbolAddress(&p_g,  d_g);

    // CSR build
    setup_kernel<<<SCAN_BLKS, 256>>>((const int*)ei);
    count_kernel<<<(EN + 255) / 256, 256>>>(ei);
    scanA_kernel<<<SCAN_BLKS, 256>>>();
    scanB_kernel<<<1, 64>>>();
    scanC_kernel<<<SCAN_BLKS, 256>>>();
    fill_kernel<<<(EN + 255) / 256, 256>>>(ei);

    // encoder: h1 = relu(x@W1 + b1) ; h2 = h1@W2 + b2 ; g = h2@Wg
    {
        dim3 grid(HIDD / 64, (NN + 63) / 64);
        gemm_bias_act<<<grid, 256>>>(x, W1, b1, (float*)p_h1, NN, HIDD, IND, 1);
    }
    {
        dim3 grid(OUTD / 64, (NN + 63) / 64);
        gemm_bias_act<<<grid, 256>>>((const float*)p_h1, W2, b2, (float*)p_h2,
                                     NN, OUTD, HIDD, 0);
    }
    {
        dim3 grid(FEAT / 64, (NN + 63) / 64);
        gemm_bias_act<<<grid, 256>>>((const float*)p_h2, Wg, nullptr, (float*)p_g,
                                     NN, FEAT, OUTD, 0);
    }

    // attention coefficients
    {
        int warps = NN * HEADS;
        attn_coef_kernel<<<(warps * 32 + 255) / 256, 256>>>(att_src, att_dst);
    }

    // softmax + aggregation, gather-based (no output atomics)
    gather_kernel<<<NN / 4, 256>>>(out, bias_g);
}

// round 7
// speedup vs baseline: 2.2036x; 1.0423x over previous
#include <cuda_runtime.h>
#include <cuda_fp16.h>
#include <math.h>

// Problem constants
static constexpr int NN   = 10000;
static constexpr int EE   = 320000;
static constexpr int EN   = EE + NN;        // edges + self loops
static constexpr int IND  = 512;
static constexpr int HIDD = 128;
static constexpr int OUTD = 128;
static constexpr int HEADS = 4;
static constexpr int GC    = 64;
static constexpr int FEAT  = HEADS * GC;    // 256
static constexpr float NEG_SLOPE = 0.2f;
static constexpr int MAXDEG = 256;          // smem cache cap (deg ~ Poisson(33))
static constexpr int SCAN_BLKS = 40;        // 40*256 = 10240 >= NN

// -------- scratch (device globals: no allocation allowed) --------
__device__ float  d_h1[(size_t)NN * HIDD];
__device__ float  d_h2[(size_t)NN * OUTD];
__device__ float  d_g [(size_t)NN * FEAT];
__device__ __half d_g16[(size_t)NN * FEAT];
__device__ float  d_asrc[NN * HEADS];
__device__ float  d_adst[NN * HEADS];
__device__ int    d_cnt[NN];          // histogram, then reused as fill cursor
__device__ int    d_off[NN + 1];      // CSR offsets
__device__ int    d_bsum[SCAN_BLKS];  // scan block partials
__device__ int    d_src_csr[EN];      // src node per CSR slot
__device__ int    d_is64;

// -------- helpers --------
__device__ __forceinline__ void load_edge(const void* ei, int is64, int tid,
                                          int& s, int& d) {
    if (tid < EE) {
        if (is64) {
            const long long* p = (const long long*)ei;
            s = (int)p[tid];
            d = (int)p[EE + tid];
        } else {
            const int* p = (const int*)ei;
            s = p[tid];
            d = p[EE + tid];
        }
    } else {
        s = d = tid - EE;
    }
}

// -------- setup: zero histogram + detect int64 vs int32 edge_index --------
__global__ void setup_kernel(const int* ei) {
    int idx = blockIdx.x * blockDim.x + threadIdx.x;
    if (idx < NN) d_cnt[idx] = 0;
    if (idx == 0) {
        int ok64 = 1;
        for (int i = 1; i < 256; i += 2)
            if (ei[i] != 0) { ok64 = 0; break; }
        d_is64 = ok64;
    }
}

__global__ void count_kernel(const void* __restrict__ ei) {
    int tid = blockIdx.x * blockDim.x + threadIdx.x;
    if (tid >= EN) return;
    int s, d;
    load_edge(ei, d_is64, tid, s, d);
    atomicAdd(&d_cnt[d], 1);
}

// -------- 3-phase exclusive scan of d_cnt -> d_off --------
__global__ void scanA_kernel() {
    __shared__ int sh[256];
    const int t = threadIdx.x;
    const int idx = blockIdx.x * 256 + t;
    int v = (idx < NN) ? d_cnt[idx] : 0;
    sh[t] = v;
    __syncthreads();
    #pragma unroll
    for (int o = 1; o < 256; o <<= 1) {
        int u = (t >= o) ? sh[t - o] : 0;
        __syncthreads();
        sh[t] += u;
        __syncthreads();
    }
    if (idx < NN) d_off[idx] = sh[t] - v;      // local exclusive
    if (t == 255) d_bsum[blockIdx.x] = sh[255];
}

__global__ void scanB_kernel() {    // 1 block, 64 threads
    __shared__ int sh[64];
    const int t = threadIdx.x;
    int v = (t < SCAN_BLKS) ? d_bsum[t] : 0;
    sh[t] = v;
    __syncthreads();
    #pragma unroll
    for (int o = 1; o < 64; o <<= 1) {
        int u = (t >= o) ? sh[t - o] : 0;
        __syncthreads();
        sh[t] += u;
        __syncthreads();
    }
    if (t < SCAN_BLKS) d_bsum[t] = sh[t] - v;  // exclusive block offsets
    if (t == 63) d_off[NN] = sh[63];           // total (= EN)
}

__global__ void scanC_kernel() {
    int idx = blockIdx.x * 256 + threadIdx.x;
    if (idx < NN) {
        d_off[idx] += d_bsum[blockIdx.x];
        d_cnt[idx] = 0;                        // reset for fill cursor
    }
}

__global__ void fill_kernel(const void* __restrict__ ei) {
    int tid = blockIdx.x * blockDim.x + threadIdx.x;
    if (tid >= EN) return;
    int s, d;
    load_edge(ei, d_is64, tid, s, d);
    int pos = atomicAdd(&d_cnt[d], 1);
    d_src_csr[d_off[d] + pos] = s;
}

// -------- tiled fp32 GEMM: C[M,Nc] = A[M,K] @ B[K,Nc] (+bias)(+relu) --------
// BM=64, BN=64, BK=16, 256 threads, 4x4 micro-tile. Optional fp16 shadow copy.
__global__ void gemm_bias_act(const float* __restrict__ A,
                              const float* __restrict__ B,
                              const float* __restrict__ bias,
                              float* __restrict__ C,
                              __half* __restrict__ C16,
                              int M, int Nc, int K, int do_relu) {
    __shared__ float As[64][17];
    __shared__ float Bs[16][64];

    const int t  = threadIdx.x;
    const int tx = t & 15;
    const int ty = t >> 4;
    const int m0 = blockIdx.y * 64;
    const int n0 = blockIdx.x * 64;

    const int aRow = t >> 2;
    const int aCol = (t & 3) * 4;
    const int bRow = t >> 4;
    const int bCol = (t & 15) * 4;

    float acc[4][4] = {};

    for (int k0 = 0; k0 < K; k0 += 16) {
        if (m0 + aRow < M) {
            float4 v = *(const float4*)&A[(size_t)(m0 + aRow) * K + k0 + aCol];
            As[aRow][aCol + 0] = v.x; As[aRow][aCol + 1] = v.y;
            As[aRow][aCol + 2] = v.z; As[aRow][aCol + 3] = v.w;
        } else {
            As[aRow][aCol + 0] = 0.f; As[aRow][aCol + 1] = 0.f;
            As[aRow][aCol + 2] = 0.f; As[aRow][aCol + 3] = 0.f;
        }
        {
            float4 v = *(const float4*)&B[(size_t)(k0 + bRow) * Nc + n0 + bCol];
            Bs[bRow][bCol + 0] = v.x; Bs[bRow][bCol + 1] = v.y;
            Bs[bRow][bCol + 2] = v.z; Bs[bRow][bCol + 3] = v.w;
        }
        __syncthreads();

        #pragma unroll
        for (int k = 0; k < 16; k++) {
            float a[4], b[4];
            #pragma unroll
            for (int i = 0; i < 4; i++) a[i] = As[ty * 4 + i][k];
            #pragma unroll
            for (int j = 0; j < 4; j++) b[j] = Bs[k][tx * 4 + j];
            #pragma unroll
            for (int i = 0; i < 4; i++)
                #pragma unroll
                for (int j = 0; j < 4; j++)
                    acc[i][j] = fmaf(a[i], b[j], acc[i][j]);
        }
        __syncthreads();
    }

    #pragma unroll
    for (int i = 0; i < 4; i++) {
        int row = m0 + ty * 4 + i;
        if (row >= M) continue;
        float o[4];
        #pragma unroll
        for (int j = 0; j < 4; j++) {
            int col = n0 + tx * 4 + j;
            float v = acc[i][j];
            if (bias) v += bias[col];
            if (do_relu) v = fmaxf(v, 0.f);
            o[j] = v;
        }
        *(float4*)&C[(size_t)row * Nc + n0 + tx * 4] =
            make_float4(o[0], o[1], o[2], o[3]);
        if (C16) {
            __half2* hp = (__half2*)&C16[(size_t)row * Nc + n0 + tx * 4];
            hp[0] = __floats2half2_rn(o[0], o[1]);
            hp[1] = __floats2half2_rn(o[2], o[3]);
        }
    }
}

// -------- per-node attention coefficients: one warp per (node, head) --------
__global__ void attn_coef_kernel(const float* __restrict__ att_src,
                                 const float* __restrict__ att_dst) {
    int warp = (blockIdx.x * blockDim.x + threadIdx.x) >> 5;
    int lane = threadIdx.x & 31;
    if (warp >= NN * HEADS) return;
    int n = warp / HEADS, h = warp % HEADS;
    const float* gp = d_g + (size_t)n * FEAT + h * GC;
    float ss = 0.f, sd = 0.f;
    #pragma unroll
    for (int c = lane; c < GC; c += 32) {
        float gv = gp[c];
        ss += gv * att_src[h * GC + c];
        sd += gv * att_dst[h * GC + c];
    }
    #pragma unroll
    for (int o = 16; o; o >>= 1) {
        ss += __shfl_xor_sync(0xFFFFFFFFu, ss, o);
        sd += __shfl_xor_sync(0xFFFFFFFFu, sd, o);
    }
    if (lane == 0) {
        d_asrc[n * HEADS + h] = ss;
        d_adst[n * HEADS + h] = sd;
    }
}

// -------- gather aggregation: two-pass, fp16 features in pass 2 --------
__global__ void __launch_bounds__(256) gather_kernel(float* __restrict__ out,
                                                     const float* __restrict__ bias_g) {
    __shared__ float s_ex[4][MAXDEG * HEADS];
    __shared__ int   s_src[4][MAXDEG];

    const int grp  = threadIdx.x >> 6;       // node slot in block
    const int t    = threadIdx.x & 63;       // channel quad owner
    const int node = blockIdx.x * 4 + grp;   // NN % 4 == 0
    const int h    = t >> 4;                 // head of my channels
    const int l16  = t & 15;

    const int beg = d_off[node];
    const int deg = d_off[node + 1] - beg;
    const int cached = (deg < MAXDEG) ? deg : MAXDEG;

    for (int j = t; j < cached; j += 64)
        s_src[grp][j] = d_src_csr[beg + j];
    __syncthreads();

    const float adst_h = d_adst[node * HEADS + h];

    // pass 1: ex per (edge, my head), partial softmax sum over 16 lanes
    float psum = 0.f;
    for (int j = l16; j < deg; j += 16) {
        int s = (j < MAXDEG) ? s_src[grp][j] : d_src_csr[beg + j];
        float e = d_asrc[s * HEADS + h] + adst_h;
        e = (e > 0.f) ? e : NEG_SLOPE * e;
        float ex = __expf(e);
        if (j < MAXDEG) s_ex[grp][j * HEADS + h] = ex;
        psum += ex;
    }
    #pragma unroll
    for (int o = 8; o; o >>= 1)
        psum += __shfl_xor_sync(0xFFFFFFFFu, psum, o);
    const float inv = __frcp_rn(psum);       // deg >= 1 (self loop)
    __syncthreads();

    // pass 2a: cached edges — clean unrolled loop, fp16 features (8B/edge/thr)
    float4 acc = make_float4(0.f, 0.f, 0.f, 0.f);
    #pragma unroll 4
    for (int j = 0; j < cached; j++) {
        float alpha = s_ex[grp][j * HEADS + h] * inv;
        int s = s_src[grp][j];
        const __half2* gp = (const __half2*)&d_g16[(size_t)s * FEAT + 4 * t];
        float2 f01 = __half22float2(gp[0]);
        float2 f23 = __half22float2(gp[1]);
        acc.x = fmaf(f01.x, alpha, acc.x);
        acc.y = fmaf(f01.y, alpha, acc.y);
        acc.z = fmaf(f23.x, alpha, acc.z);
        acc.w = fmaf(f23.y, alpha, acc.w);
    }
    // pass 2b: spill edges (deg > MAXDEG, rare)
    for (int j = cached; j < deg; j++) {
        int s = d_src_csr[beg + j];
        float e = d_asrc[s * HEADS + h] + adst_h;
        e = (e > 0.f) ? e : NEG_SLOPE * e;
        float alpha = __expf(e) * inv;
        const __half2* gp = (const __half2*)&d_g16[(size_t)s * FEAT + 4 * t];
        float2 f01 = __half22float2(gp[0]);
        float2 f23 = __half22float2(gp[1]);
        acc.x = fmaf(f01.x, alpha, acc.x);
        acc.y = fmaf(f01.y, alpha, acc.y);
        acc.z = fmaf(f23.x, alpha, acc.z);
        acc.w = fmaf(f23.y, alpha, acc.w);
    }

    float4 bv = *(const float4*)&bias_g[4 * t];
    acc.x += bv.x; acc.y += bv.y; acc.z += bv.z; acc.w += bv.w;
    *(float4*)&out[(size_t)node * FEAT + 4 * t] = acc;
}

// ----------------------------------------------------------------------------
extern "C" void kernel_launch(void* const* d_in, const int* in_sizes, int n_in,
                              void* d_out, int out_size) {
    const float* x        = (const float*)d_in[0];
    const void*  ei       = d_in[1];
    const float* W1       = (const float*)d_in[2];
    const float* b1       = (const float*)d_in[3];
    const float* W2       = (const float*)d_in[4];
    const float* b2       = (const float*)d_in[5];
    const float* Wg       = (const float*)d_in[6];
    const float* att_src  = (const float*)d_in[7];
    const float* att_dst  = (const float*)d_in[8];
    const float* bias_g   = (const float*)d_in[9];
    float* out = (float*)d_out;

    void *p_h1, *p_h2, *p_g, *p_g16;
    cudaGetSymbolAddress(&p_h1, d_h1);
    cudaGetSymbolAddress(&p_h2, d_h2);
    cudaGetSymbolAddress(&p_g,  d_g);
    cudaGetSymbolAddress(&p_g16, d_g16);

    // CSR build
    setup_kernel<<<SCAN_BLKS, 256>>>((const int*)ei);
    count_kernel<<<(EN + 255) / 256, 256>>>(ei);
    scanA_kernel<<<SCAN_BLKS, 256>>>();
    scanB_kernel<<<1, 64>>>();
    scanC_kernel<<<SCAN_BLKS, 256>>>();
    fill_kernel<<<(EN + 255) / 256, 256>>>(ei);

    // encoder: h1 = relu(x@W1 + b1) ; h2 = h1@W2 + b2 ; g = h2@Wg (+fp16 copy)
    {
        dim3 grid(HIDD / 64, (NN + 63) / 64);
        gemm_bias_act<<<grid, 256>>>(x, W1, b1, (float*)p_h1, nullptr,
                                     NN, HIDD, IND, 1);
    }
    {
        dim3 grid(OUTD / 64, (NN + 63) / 64);
        gemm_bias_act<<<grid, 256>>>((const float*)p_h1, W2, b2, (float*)p_h2,
                                     nullptr, NN, OUTD, HIDD, 0);
    }
    {
        dim3 grid(FEAT / 64, (NN + 63) / 64);
        gemm_bias_act<<<grid, 256>>>((const float*)p_h2, Wg, nullptr, (float*)p_g,
                                     (__half*)p_g16, NN, FEAT, OUTD, 0);
    }

    // attention coefficients (fp32 path, unchanged)
    {
        int warps = NN * HEADS;
        attn_coef_kernel<<<(warps * 32 + 255) / 256, 256>>>(att_src, att_dst);
    }

    // softmax + aggregation, gather-based (no output atomics)
    gather_kernel<<<NN / 4, 256>>>(out, bias_g);
}